// round 1
// baseline (speedup 1.0000x reference)
#include <cuda_runtime.h>
#include <cuda_bf16.h>
#include <math.h>

// Problem constants
#define NB     32      // batch
#define HQ     32
#define HKV    8
#define NREP   4
#define HD     128
#define DIM    4096    // HQ*HD
#define KVD    1024    // HKV*HD
#define MAXSEQ 4096
#define SEQ    4096    // start_pos + 1
#define NEWPOS 4095

#define KSPLIT 4       // GEMM k-split
#define QKV_OUTS 6144  // 4096 + 1024 + 1024
#define NSPLIT 8       // attention seq splits
#define SCHUNK 512     // 4096 / 8

// ---------------- scratch (device globals; no allocations allowed) -------------
__device__ float g_qkvp[KSPLIT * NB * QKV_OUTS];   // qkv gemm partials
__device__ float g_q   [NB * DIM];                  // rope'd q
__device__ float g_kn  [NB * KVD];                  // rope'd new k
__device__ float g_vn  [NB * KVD];                  // new v
__device__ float g_pm  [NB * HKV * NSPLIT * NREP];  // partial max
__device__ float g_pl  [NB * HKV * NSPLIT * NREP];  // partial sum
__device__ float g_pacc[NB * HKV * NSPLIT * NREP * HD]; // partial acc
__device__ float g_attn[NB * DIM];                  // attention output
__device__ float g_op  [KSPLIT * NB * DIM];         // wo gemm partials

// ------------------------------------------------------------------------------
// GEMM: y[b,o] = sum_k x[b,k] * W[o,k].  K = 4096 always, B = 32.
// grid: (OUTS/128, KSPLIT), 128 threads.
// Thread tile: 4 outs x 8 batches. smem stored k-major for conflict-free float4.
// Weight row selection across up to 3 concatenated weight matrices (wq|wk|wv).
// ------------------------------------------------------------------------------
__global__ __launch_bounds__(128, 8)
void gemm_xwT(const float* __restrict__ x,
              const float* __restrict__ w0,
              const float* __restrict__ w1,
              const float* __restrict__ w2,
              int n0, int n1,
              float* __restrict__ yp, int OUTS)
{
    const int obase = blockIdx.x * 128;
    const float* wp;
    int orow;
    if (obase < n0)            { wp = w0; orow = obase; }
    else if (obase < n0 + n1)  { wp = w1; orow = obase - n0; }
    else                       { wp = w2; orow = obase - n0 - n1; }
    const int kb = blockIdx.y * (4096 / KSPLIT);

    __shared__ float ws[16][132];  // [k][o], row stride 132 (16B-aligned)
    __shared__ float xs[16][36];   // [k][b]

    const int t  = threadIdx.x;
    const int og = t & 31;   // out group: outs = og*4 + j
    const int bg = t >> 5;   // batch group: b = bg*8 + i

    const int lb = t >> 2;        // 0..31 (load row)
    const int lk = (t & 3) * 4;   // 0,4,8,12 (load k-offset)

    float acc[4][8];
#pragma unroll
    for (int j = 0; j < 4; j++)
#pragma unroll
        for (int i = 0; i < 8; i++) acc[j][i] = 0.f;

    for (int kt = 0; kt < (4096 / KSPLIT) / 16; kt++) {
        const int kbase = kb + kt * 16;

        // stage loads in registers (no smem touched yet)
        float4 xv = *(const float4*)&x[lb * 4096 + kbase + lk];
        float4 wv[4];
#pragma unroll
        for (int p = 0; p < 4; p++) {
            int o = lb + p * 32;
            wv[p] = *(const float4*)&wp[(orow + o) * 4096 + kbase + lk];
        }

        __syncthreads();   // previous tile's compute done
        xs[lk + 0][lb] = xv.x;
        xs[lk + 1][lb] = xv.y;
        xs[lk + 2][lb] = xv.z;
        xs[lk + 3][lb] = xv.w;
#pragma unroll
        for (int p = 0; p < 4; p++) {
            int o = lb + p * 32;
            ws[lk + 0][o] = wv[p].x;
            ws[lk + 1][o] = wv[p].y;
            ws[lk + 2][o] = wv[p].z;
            ws[lk + 3][o] = wv[p].w;
        }
        __syncthreads();

#pragma unroll
        for (int kk = 0; kk < 16; kk++) {
            float4 w4 = *(const float4*)&ws[kk][og * 4];
            float4 xa = *(const float4*)&xs[kk][bg * 8];
            float4 xb = *(const float4*)&xs[kk][bg * 8 + 4];
            acc[0][0] += w4.x * xa.x; acc[0][1] += w4.x * xa.y;
            acc[0][2] += w4.x * xa.z; acc[0][3] += w4.x * xa.w;
            acc[0][4] += w4.x * xb.x; acc[0][5] += w4.x * xb.y;
            acc[0][6] += w4.x * xb.z; acc[0][7] += w4.x * xb.w;
            acc[1][0] += w4.y * xa.x; acc[1][1] += w4.y * xa.y;
            acc[1][2] += w4.y * xa.z; acc[1][3] += w4.y * xa.w;
            acc[1][4] += w4.y * xb.x; acc[1][5] += w4.y * xb.y;
            acc[1][6] += w4.y * xb.z; acc[1][7] += w4.y * xb.w;
            acc[2][0] += w4.z * xa.x; acc[2][1] += w4.z * xa.y;
            acc[2][2] += w4.z * xa.z; acc[2][3] += w4.z * xa.w;
            acc[2][4] += w4.z * xb.x; acc[2][5] += w4.z * xb.y;
            acc[2][6] += w4.z * xb.z; acc[2][7] += w4.z * xb.w;
            acc[3][0] += w4.w * xa.x; acc[3][1] += w4.w * xa.y;
            acc[3][2] += w4.w * xa.z; acc[3][3] += w4.w * xa.w;
            acc[3][4] += w4.w * xb.x; acc[3][5] += w4.w * xb.y;
            acc[3][6] += w4.w * xb.z; acc[3][7] += w4.w * xb.w;
        }
    }

#pragma unroll
    for (int j = 0; j < 4; j++) {
        const int o = obase + og * 4 + j;
#pragma unroll
        for (int i = 0; i < 8; i++) {
            const int b = bg * 8 + i;
            yp[(blockIdx.y * NB + b) * OUTS + o] = acc[j][i];
        }
    }
}

// ------------------------------------------------------------------------------
// RoPE + k-split reduce. Processes element pairs.
// qkvp[s][b][j], j<4096 -> q, 4096..5119 -> k, 5120.. -> v.
// grid 384 x 256 (exactly 32*3072 pairs).
// ------------------------------------------------------------------------------
__global__ void rope_reduce(const float* __restrict__ qkvp,
                            const float* __restrict__ fc,
                            const float* __restrict__ fs,
                            float* __restrict__ qout,
                            float* __restrict__ kout,
                            float* __restrict__ vout)
{
    const int idx = blockIdx.x * 256 + threadIdx.x;  // < 98304
    const int b  = idx / 3072;
    const int jp = idx % 3072;
    const int j0 = jp * 2;

    float v0 = 0.f, v1 = 0.f;
#pragma unroll
    for (int s = 0; s < KSPLIT; s++) {
        const float* p = qkvp + (s * NB + b) * QKV_OUTS + j0;
        v0 += p[0];
        v1 += p[1];
    }
    if (j0 < DIM + KVD) {  // q and k get RoPE
        const int i = jp & 63;     // pair index within head
        const float c = fc[i], s_ = fs[i];
        const float re = v0 * c - v1 * s_;
        const float im = v0 * s_ + v1 * c;
        v0 = re; v1 = im;
    }
    if (j0 < DIM) {
        qout[b * DIM + j0] = v0;
        qout[b * DIM + j0 + 1] = v1;
    } else if (j0 < DIM + KVD) {
        kout[b * KVD + (j0 - DIM)] = v0;
        kout[b * KVD + (j0 - DIM) + 1] = v1;
    } else {
        vout[b * KVD + (j0 - DIM - KVD)] = v0;
        vout[b * KVD + (j0 - DIM - KVD) + 1] = v1;
    }
}

// ------------------------------------------------------------------------------
// Flash-decode split attention. grid (256, 8): x = b*8+g, y = split. 256 threads.
// Position 4095 (stale cache) is masked out; new token handled in combine.
// ------------------------------------------------------------------------------
__global__ __launch_bounds__(256, 6)
void attn_split(const float* __restrict__ q,
                const float* __restrict__ ck,
                const float* __restrict__ cv,
                float* __restrict__ pm,
                float* __restrict__ pl,
                float* __restrict__ pacc)
{
    const int bg = blockIdx.x;
    const int b = bg >> 3, g = bg & 7;
    const int split = blockIdx.y;
    const int t = threadIdx.x;
    const int lane = t & 31, w = t >> 5;

    __shared__ float qs[4][HD];
    __shared__ float sc[4][SCHUNK];
    __shared__ float red[8][4];
    __shared__ float mf[4];
    __shared__ float accsm[4][HD];

    const float scale = 0.08838834764831845f;  // 1/sqrt(128)

    for (int idx = t; idx < 4 * HD; idx += 256) {
        const int r = idx >> 7, d = idx & 127;
        qs[r][d] = q[(b * HQ + g * NREP + r) * HD + d] * scale;
    }
    __syncthreads();

    // hoisted q fragments for this lane
    const float4 q0 = *(const float4*)&qs[0][lane * 4];
    const float4 q1 = *(const float4*)&qs[1][lane * 4];
    const float4 q2 = *(const float4*)&qs[2][lane * 4];
    const float4 q3 = *(const float4*)&qs[3][lane * 4];

    const int sbase = split * SCHUNK;
    float wm0 = -1e30f, wm1 = -1e30f, wm2 = -1e30f, wm3 = -1e30f;

    for (int i = 0; i < 64; i++) {
        const int sl = w * 64 + i;
        const int s = sbase + sl;
        const float4 k4 = *(const float4*)&ck[(b * MAXSEQ + s) * KVD + g * HD + lane * 4];
        float d0 = k4.x * q0.x + k4.y * q0.y + k4.z * q0.z + k4.w * q0.w;
        float d1 = k4.x * q1.x + k4.y * q1.y + k4.z * q1.z + k4.w * q1.w;
        float d2 = k4.x * q2.x + k4.y * q2.y + k4.z * q2.z + k4.w * q2.w;
        float d3 = k4.x * q3.x + k4.y * q3.y + k4.z * q3.z + k4.w * q3.w;
#pragma unroll
        for (int off = 16; off > 0; off >>= 1) {
            d0 += __shfl_xor_sync(0xffffffffu, d0, off);
            d1 += __shfl_xor_sync(0xffffffffu, d1, off);
            d2 += __shfl_xor_sync(0xffffffffu, d2, off);
            d3 += __shfl_xor_sync(0xffffffffu, d3, off);
        }
        if (s == NEWPOS) { d0 = d1 = d2 = d3 = -1e30f; }  // stale cache entry masked
        if (lane == 0) {
            sc[0][sl] = d0; sc[1][sl] = d1; sc[2][sl] = d2; sc[3][sl] = d3;
        }
        wm0 = fmaxf(wm0, d0); wm1 = fmaxf(wm1, d1);
        wm2 = fmaxf(wm2, d2); wm3 = fmaxf(wm3, d3);
    }
    if (lane == 0) { red[w][0] = wm0; red[w][1] = wm1; red[w][2] = wm2; red[w][3] = wm3; }
    __syncthreads();
    if (t < 4) {
        float m = red[0][t];
#pragma unroll
        for (int j = 1; j < 8; j++) m = fmaxf(m, red[j][t]);
        mf[t] = m;
    }
    __syncthreads();

    // exponentiate + row sums
    float ls0 = 0.f, ls1 = 0.f, ls2 = 0.f, ls3 = 0.f;
    for (int idx = t; idx < 4 * SCHUNK; idx += 256) {
        const int r = idx >> 9, sl = idx & 511;
        const float p = __expf(sc[r][sl] - mf[r]);
        sc[r][sl] = p;
        if (r == 0) ls0 += p; else if (r == 1) ls1 += p;
        else if (r == 2) ls2 += p; else ls3 += p;
    }
#pragma unroll
    for (int off = 16; off > 0; off >>= 1) {
        ls0 += __shfl_xor_sync(0xffffffffu, ls0, off);
        ls1 += __shfl_xor_sync(0xffffffffu, ls1, off);
        ls2 += __shfl_xor_sync(0xffffffffu, ls2, off);
        ls3 += __shfl_xor_sync(0xffffffffu, ls3, off);
    }
    if (lane == 0) { red[w][0] = ls0; red[w][1] = ls1; red[w][2] = ls2; red[w][3] = ls3; }
    __syncthreads();
    if (t < 4) {
        float L = 0.f;
#pragma unroll
        for (int j = 0; j < 8; j++) L += red[j][t];
        pm[bg * (NSPLIT * NREP) + split * NREP + t] = mf[t];
        pl[bg * (NSPLIT * NREP) + split * NREP + t] = L;
    }
    __syncthreads();

    // P @ V  (two s-halves per d)
    const int d = t & 127, h2 = t >> 7;
    float a0 = 0.f, a1 = 0.f, a2 = 0.f, a3 = 0.f;
    for (int i = 0; i < 256; i++) {
        const int sl = h2 * 256 + i;
        const int s = sbase + sl;
        const float v = cv[(b * MAXSEQ + s) * KVD + g * HD + d];
        a0 += sc[0][sl] * v; a1 += sc[1][sl] * v;
        a2 += sc[2][sl] * v; a3 += sc[3][sl] * v;
    }
    if (h2 == 0) { accsm[0][d] = a0; accsm[1][d] = a1; accsm[2][d] = a2; accsm[3][d] = a3; }
    __syncthreads();
    if (h2 == 1) { accsm[0][d] += a0; accsm[1][d] += a1; accsm[2][d] += a2; accsm[3][d] += a3; }
    __syncthreads();
    if (t < 128) {
        const int base = ((bg * NSPLIT + split) * NREP) * HD + d;
#pragma unroll
        for (int r = 0; r < 4; r++) pacc[base + r * HD] = accsm[r][d];
    }
}

// ------------------------------------------------------------------------------
// Combine partials + new token (s=4095). grid 256 (b*8+g), 128 threads (d).
// ------------------------------------------------------------------------------
__global__ void attn_combine(const float* __restrict__ q,
                             const float* __restrict__ kn,
                             const float* __restrict__ vn,
                             const float* __restrict__ pm,
                             const float* __restrict__ pl,
                             const float* __restrict__ pacc,
                             float* __restrict__ attn)
{
    const int bg = blockIdx.x;
    const int b = bg >> 3, g = bg & 7;
    const int t = threadIdx.x, lane = t & 31, r = t >> 5;
    __shared__ float sn[4];
    const float scale = 0.08838834764831845f;

    // score of the new token per rep-head (one warp each)
    {
        const float4 k4 = *(const float4*)&kn[(b * HKV + g) * HD + lane * 4];
        const float4 q4 = *(const float4*)&q[(b * HQ + g * NREP + r) * HD + lane * 4];
        float ds = k4.x * q4.x + k4.y * q4.y + k4.z * q4.z + k4.w * q4.w;
#pragma unroll
        for (int off = 16; off > 0; off >>= 1) ds += __shfl_xor_sync(0xffffffffu, ds, off);
        if (lane == 0) sn[r] = ds * scale;
    }
    __syncthreads();

    const int d = t;  // 0..127
    const float vnew = vn[(b * HKV + g) * HD + d];

#pragma unroll
    for (int rr = 0; rr < 4; rr++) {
        float mi[NSPLIT];
        float M = sn[rr];
#pragma unroll
        for (int i = 0; i < NSPLIT; i++) {
            mi[i] = pm[bg * (NSPLIT * NREP) + i * NREP + rr];
            M = fmaxf(M, mi[i]);
        }
        const float en = __expf(sn[rr] - M);
        float L = en;
        float num = en * vnew;
#pragma unroll
        for (int i = 0; i < NSPLIT; i++) {
            const float e = __expf(mi[i] - M);
            L += pl[bg * (NSPLIT * NREP) + i * NREP + rr] * e;
            num += pacc[((bg * NSPLIT + i) * NREP + rr) * HD + d] * e;
        }
        attn[(b * HQ + g * NREP + rr) * HD + d] = num / L;
    }
}

// ------------------------------------------------------------------------------
// Final k-split reduce of wo GEMM partials -> d_out.  grid 512 x 256.
// ------------------------------------------------------------------------------
__global__ void final_reduce(const float* __restrict__ op, float* __restrict__ out)
{
    const int idx = blockIdx.x * 256 + threadIdx.x;  // < 131072
    out[idx] = op[idx] + op[idx + NB * DIM] + op[idx + 2 * NB * DIM] + op[idx + 3 * NB * DIM];
}

// ------------------------------------------------------------------------------
extern "C" void kernel_launch(void* const* d_in, const int* in_sizes, int n_in,
                              void* d_out, int out_size)
{
    const float* x  = (const float*)d_in[0];
    const float* ck = (const float*)d_in[1];
    const float* cv = (const float*)d_in[2];
    const float* wq = (const float*)d_in[3];
    const float* wk = (const float*)d_in[4];
    const float* wv = (const float*)d_in[5];
    const float* wo = (const float*)d_in[6];
    const float* fc = (const float*)d_in[7];
    const float* fs = (const float*)d_in[8];
    float* out = (float*)d_out;

    float *qkvp, *qb, *kn, *vn, *pm, *pl, *pacc, *attn, *op;
    cudaGetSymbolAddress((void**)&qkvp, g_qkvp);
    cudaGetSymbolAddress((void**)&qb,   g_q);
    cudaGetSymbolAddress((void**)&kn,   g_kn);
    cudaGetSymbolAddress((void**)&vn,   g_vn);
    cudaGetSymbolAddress((void**)&pm,   g_pm);
    cudaGetSymbolAddress((void**)&pl,   g_pl);
    cudaGetSymbolAddress((void**)&pacc, g_pacc);
    cudaGetSymbolAddress((void**)&attn, g_attn);
    cudaGetSymbolAddress((void**)&op,   g_op);

    // 1) fused QKV projection (k-split partials)
    gemm_xwT<<<dim3(QKV_OUTS / 128, KSPLIT), 128>>>(x, wq, wk, wv, DIM, KVD, qkvp, QKV_OUTS);
    // 2) reduce partials + RoPE
    rope_reduce<<<384, 256>>>(qkvp, fc, fs, qb, kn, vn);
    // 3) split attention over cached tokens (pos 4095 masked)
    attn_split<<<dim3(NB * HKV, NSPLIT), 256>>>(qb, ck, cv, pm, pl, pacc);
    // 4) combine + new token
    attn_combine<<<NB * HKV, 128>>>(qb, kn, vn, pm, pl, pacc, attn);
    // 5) output projection (k-split partials)
    gemm_xwT<<<dim3(DIM / 128, KSPLIT), 128>>>(attn, wo, wo, wo, DIM, 0, op, DIM);
    // 6) reduce to d_out
    final_reduce<<<512, 256>>>(op, out);
}

// round 2
// speedup vs baseline: 1.3837x; 1.3837x over previous
#include <cuda_runtime.h>
#include <cuda_bf16.h>
#include <math.h>

// Problem constants
#define NB     32      // batch
#define HQ     32
#define HKV    8
#define NREP   4
#define HD     128
#define DIM    4096    // HQ*HD
#define KVD    1024    // HKV*HD
#define MAXSEQ 4096
#define NEWPOS 4095

#define KSPLIT 8       // GEMM k-split
#define KB     512     // 4096 / KSPLIT
#define QKV_OUTS 6144  // 4096 + 1024 + 1024
#define NSPLIT 8       // attention seq splits
#define SCHUNK 512     // 4096 / 8

// ---------------- scratch (device globals; no allocations allowed) -------------
__device__ float g_qkvp[KSPLIT * NB * QKV_OUTS];   // qkv gemm partials
__device__ float g_q   [NB * DIM];                  // rope'd q
__device__ float g_kn  [NB * KVD];                  // rope'd new k
__device__ float g_vn  [NB * KVD];                  // new v
__device__ float g_pm  [NB * HKV * NSPLIT * NREP];  // partial max
__device__ float g_pl  [NB * HKV * NSPLIT * NREP];  // partial sum
__device__ float g_pacc[NB * HKV * NSPLIT * NREP * HD]; // partial acc
__device__ float g_attn[NB * DIM];                  // attention output
__device__ float g_op  [KSPLIT * NB * DIM];         // wo gemm partials

// ---------------- f32x2 helpers -------------------------------------------------
__device__ __forceinline__ unsigned long long f2fma(unsigned long long a,
                                                    unsigned long long b,
                                                    unsigned long long c) {
    unsigned long long d;
    asm("fma.rn.f32x2 %0, %1, %2, %3;" : "=l"(d) : "l"(a), "l"(b), "l"(c));
    return d;
}
__device__ __forceinline__ float2 uf2(unsigned long long u) {
    float2 f;
    asm("mov.b64 {%0, %1}, %2;" : "=f"(f.x), "=f"(f.y) : "l"(u));
    return f;
}

// ------------------------------------------------------------------------------
// GEMM: y[b,o] = sum_k x[b,k] * W[o,k].  K = 4096, B = 32, f32x2 math.
// grid: (OUTS/128, KSPLIT), 256 threads. Thread tile: 4 outs x 4 batches.
// w pairs along out dim (natural from float4 load); x duplicated in smem.
// ------------------------------------------------------------------------------
__global__ __launch_bounds__(256)
void gemm_xwT(const float* __restrict__ x,
              const float* __restrict__ w0,
              const float* __restrict__ w1,
              const float* __restrict__ w2,
              int n0, int n1,
              float* __restrict__ yp, int OUTS)
{
    const int obase = blockIdx.x * 128;
    const float* wp;
    int orow;
    if (obase < n0)            { wp = w0; orow = obase; }
    else if (obase < n0 + n1)  { wp = w1; orow = obase - n0; }
    else                       { wp = w2; orow = obase - n0 - n1; }
    const int kb0 = blockIdx.y * KB;

    __shared__ __align__(16) float ws[16 * 132];   // [k][o]
    __shared__ __align__(16) float xs2[16 * 68];   // [k][b dup pairs]

    const int t   = threadIdx.x;
    const int og  = t & 31;   // outs = og*4 + {0..3}
    const int bgp = t >> 5;   // batches = bgp*4 + {0..3}

    // load indices
    const int lxb = t >> 2;          // x: batch row (t<128)
    const int lxk = (t & 3) * 4;     // x: k offset

    unsigned long long acc2[2][4];   // [o-pair][batch]
#pragma unroll
    for (int p = 0; p < 2; p++)
#pragma unroll
        for (int i = 0; i < 4; i++) acc2[p][i] = 0ull;

    for (int kt = 0; kt < KB / 16; kt++) {
        const int kbase = kb0 + kt * 16;

        // stage loads in registers
        float4 xv = make_float4(0.f, 0.f, 0.f, 0.f);
        if (t < 128) xv = *(const float4*)&x[lxb * 4096 + kbase + lxk];
        float4 wv[2];
        int wo_[2], wk_[2];
#pragma unroll
        for (int p = 0; p < 2; p++) {
            int idx = t + p * 256;            // 0..511
            wo_[p] = idx >> 2;                // 0..127
            wk_[p] = (idx & 3) * 4;
            wv[p] = *(const float4*)&wp[(orow + wo_[p]) * 4096 + kbase + wk_[p]];
        }

        __syncthreads();   // previous tile's compute done
        if (t < 128) {
            xs2[(lxk + 0) * 68 + lxb * 2] = xv.x; xs2[(lxk + 0) * 68 + lxb * 2 + 1] = xv.x;
            xs2[(lxk + 1) * 68 + lxb * 2] = xv.y; xs2[(lxk + 1) * 68 + lxb * 2 + 1] = xv.y;
            xs2[(lxk + 2) * 68 + lxb * 2] = xv.z; xs2[(lxk + 2) * 68 + lxb * 2 + 1] = xv.z;
            xs2[(lxk + 3) * 68 + lxb * 2] = xv.w; xs2[(lxk + 3) * 68 + lxb * 2 + 1] = xv.w;
        }
#pragma unroll
        for (int p = 0; p < 2; p++) {
            ws[(wk_[p] + 0) * 132 + wo_[p]] = wv[p].x;
            ws[(wk_[p] + 1) * 132 + wo_[p]] = wv[p].y;
            ws[(wk_[p] + 2) * 132 + wo_[p]] = wv[p].z;
            ws[(wk_[p] + 3) * 132 + wo_[p]] = wv[p].w;
        }
        __syncthreads();

#pragma unroll
        for (int kk = 0; kk < 16; kk++) {
            ulonglong2 w2 = *(const ulonglong2*)&ws[kk * 132 + og * 4];
#pragma unroll
            for (int i = 0; i < 4; i++) {
                unsigned long long xp = *(const unsigned long long*)&xs2[kk * 68 + (bgp * 4 + i) * 2];
                acc2[0][i] = f2fma(w2.x, xp, acc2[0][i]);
                acc2[1][i] = f2fma(w2.y, xp, acc2[1][i]);
            }
        }
    }

#pragma unroll
    for (int p = 0; p < 2; p++) {
#pragma unroll
        for (int i = 0; i < 4; i++) {
            float2 f = uf2(acc2[p][i]);
            const int o = obase + og * 4 + p * 2;
            const int b = bgp * 4 + i;
            yp[(blockIdx.y * NB + b) * OUTS + o]     = f.x;
            yp[(blockIdx.y * NB + b) * OUTS + o + 1] = f.y;
        }
    }
}

// ------------------------------------------------------------------------------
// RoPE + k-split reduce. grid 384 x 256.
// ------------------------------------------------------------------------------
__global__ void rope_reduce(const float* __restrict__ qkvp,
                            const float* __restrict__ fc,
                            const float* __restrict__ fs,
                            float* __restrict__ qout,
                            float* __restrict__ kout,
                            float* __restrict__ vout)
{
    const int idx = blockIdx.x * 256 + threadIdx.x;  // < 98304
    const int b  = idx / 3072;
    const int jp = idx % 3072;
    const int j0 = jp * 2;

    float v0 = 0.f, v1 = 0.f;
#pragma unroll
    for (int s = 0; s < KSPLIT; s++) {
        const float* p = qkvp + (s * NB + b) * QKV_OUTS + j0;
        v0 += p[0];
        v1 += p[1];
    }
    if (j0 < DIM + KVD) {
        const int i = jp & 63;
        const float c = fc[i], s_ = fs[i];
        const float re = v0 * c - v1 * s_;
        const float im = v0 * s_ + v1 * c;
        v0 = re; v1 = im;
    }
    if (j0 < DIM) {
        qout[b * DIM + j0] = v0;
        qout[b * DIM + j0 + 1] = v1;
    } else if (j0 < DIM + KVD) {
        kout[b * KVD + (j0 - DIM)] = v0;
        kout[b * KVD + (j0 - DIM) + 1] = v1;
    } else {
        vout[b * KVD + (j0 - DIM - KVD)] = v0;
        vout[b * KVD + (j0 - DIM - KVD) + 1] = v1;
    }
}

// ------------------------------------------------------------------------------
// Flash-decode split attention v2. grid (256, 8), 256 threads.
// QK: smem-staged K tiles of 32 s; thread = (s, d-group); K read once, reused
// across 4 rep-heads. PV: float4 V + f32x2. Pos 4095 masked (handled in combine).
// ------------------------------------------------------------------------------
__global__ __launch_bounds__(256)
void attn_split(const float* __restrict__ q,
                const float* __restrict__ ck,
                const float* __restrict__ cv,
                float* __restrict__ pm,
                float* __restrict__ pl,
                float* __restrict__ pacc)
{
    const int bg = blockIdx.x;
    const int b = bg >> 3, g = bg & 7;
    const int split = blockIdx.y;
    const int t = threadIdx.x;
    const int lane = t & 31, w = t >> 5;
    const int sbase = split * SCHUNK;

    __shared__ __align__(16) float sm[9872];
    float* qs   = sm;            // [4][128]            (512)
    float* ks   = sm + 512;      // [32][132]           (4224)  aliased by pvpart [8][4][128]
    float* scd  = sm + 4736;     // [4][1024] dup pairs (4096)
    float* part = sm + 8832;     // [8][4][32]          (1024)
    float* mf   = sm + 9856;     // [4]

    const float scale = 0.08838834764831845f;  // 1/sqrt(128)

    // q staging (pre-scaled)
    for (int i = t; i < 512; i += 256) {
        const int r = i >> 7, d = i & 127;
        qs[r * 128 + d] = q[(b * HQ + g * NREP + r) * HD + d] * scale;
    }

    float mloc = -1e30f;
    const int s_loc = t & 31;
    const int dg = t >> 5;
    const int base_d = dg * 16;

    for (int tile = 0; tile < 16; tile++) {
        __syncthreads();
        // stage K[32][128] coalesced
#pragma unroll
        for (int i = 0; i < 4; i++) {
            const int f4 = t + i * 256;
            const int row = f4 >> 5, c4 = (f4 & 31) * 4;
            float4 kv = *(const float4*)&ck[(size_t)(b * MAXSEQ + sbase + tile * 32 + row) * KVD + g * HD + c4];
            *(float4*)&ks[row * 132 + c4] = kv;
        }
        __syncthreads();

        unsigned long long racc[4] = {0ull, 0ull, 0ull, 0ull};
#pragma unroll
        for (int c = 0; c < 4; c++) {
            ulonglong2 kk = *(const ulonglong2*)&ks[s_loc * 132 + base_d + c * 4];
#pragma unroll
            for (int r = 0; r < 4; r++) {
                ulonglong2 qq = *(const ulonglong2*)&qs[r * 128 + base_d + c * 4];
                racc[r] = f2fma(kk.x, qq.x, racc[r]);
                racc[r] = f2fma(kk.y, qq.y, racc[r]);
            }
        }
#pragma unroll
        for (int r = 0; r < 4; r++) {
            float2 f = uf2(racc[r]);
            part[(dg * 4 + r) * 32 + s_loc] = f.x + f.y;
        }
        __syncthreads();
        if (t < 128) {
            const int r = t >> 5;
            float val = 0.f;
#pragma unroll
            for (int d8 = 0; d8 < 8; d8++) val += part[(d8 * 4 + r) * 32 + lane];
            const int sg = sbase + tile * 32 + lane;
            if (sg == NEWPOS) val = -1e30f;
            scd[r * 1024 + (tile * 32 + lane) * 2] = val;
            mloc = fmaxf(mloc, val);
        }
    }

    // per-rep max
    if (t < 128) {
#pragma unroll
        for (int off = 16; off; off >>= 1)
            mloc = fmaxf(mloc, __shfl_xor_sync(0xffffffffu, mloc, off));
        if (lane == 0) mf[t >> 5] = mloc;
    }
    __syncthreads();

    // exp + row sums (duplicate probs for f32x2 PV)
    {
        const int r = t >> 6, s0 = t & 63;
        const float m = mf[r];
        float ls = 0.f;
#pragma unroll
        for (int j = 0; j < 8; j++) {
            const int sl = s0 + j * 64;
            const float p = __expf(scd[r * 1024 + sl * 2] - m);
            scd[r * 1024 + sl * 2]     = p;
            scd[r * 1024 + sl * 2 + 1] = p;
            ls += p;
        }
#pragma unroll
        for (int off = 16; off; off >>= 1)
            ls += __shfl_xor_sync(0xffffffffu, ls, off);
        if (lane == 0) part[w] = ls;
    }
    __syncthreads();
    if (t < 4) {
        pm[bg * (NSPLIT * NREP) + split * NREP + t] = mf[t];
        pl[bg * (NSPLIT * NREP) + split * NREP + t] = part[2 * t] + part[2 * t + 1];
    }

    // P @ V : thread = (d-quarter, s-group of 64)
    float* pvp = ks;   // alias, [8][4][128]
    {
        const int dq = lane;     // d = dq*4 .. +3
        const int sg8 = w;       // s-group
        unsigned long long a[4][2];
#pragma unroll
        for (int r = 0; r < 4; r++) { a[r][0] = 0ull; a[r][1] = 0ull; }
        for (int i = 0; i < 64; i++) {
            const int sl = sg8 * 64 + i;
            const int s = sbase + sl;
            ulonglong2 vv = *(const ulonglong2*)&cv[(size_t)(b * MAXSEQ + s) * KVD + g * HD + dq * 4];
#pragma unroll
            for (int r = 0; r < 4; r++) {
                unsigned long long pp = *(const unsigned long long*)&scd[r * 1024 + sl * 2];
                a[r][0] = f2fma(pp, vv.x, a[r][0]);
                a[r][1] = f2fma(pp, vv.y, a[r][1]);
            }
        }
#pragma unroll
        for (int r = 0; r < 4; r++) {
            float2 f0 = uf2(a[r][0]), f1 = uf2(a[r][1]);
            float4 o4 = make_float4(f0.x, f0.y, f1.x, f1.y);
            *(float4*)&pvp[(sg8 * 4 + r) * 128 + dq * 4] = o4;
        }
    }
    __syncthreads();
#pragma unroll
    for (int i = 0; i < 2; i++) {
        const int idx = t + i * 256;   // 512 outputs
        const int r = idx >> 7, d = idx & 127;
        float v = 0.f;
#pragma unroll
        for (int sgp = 0; sgp < 8; sgp++) v += pvp[(sgp * 4 + r) * 128 + d];
        pacc[((bg * NSPLIT + split) * NREP + r) * HD + d] = v;
    }
}

// ------------------------------------------------------------------------------
// Combine partials + new token (s=4095). grid 256, 512 threads: t -> (rep, d).
// ------------------------------------------------------------------------------
__global__ __launch_bounds__(512)
void attn_combine(const float* __restrict__ q,
                  const float* __restrict__ kn,
                  const float* __restrict__ vn,
                  const float* __restrict__ pm,
                  const float* __restrict__ pl,
                  const float* __restrict__ pacc,
                  float* __restrict__ attn)
{
    const int bg = blockIdx.x;
    const int b = bg >> 3, g = bg & 7;
    const int t = threadIdx.x, lane = t & 31;
    __shared__ float sn[4];
    const float scale = 0.08838834764831845f;

    if (t < 128) {
        const int r = t >> 5;
        const float4 k4 = *(const float4*)&kn[(b * HKV + g) * HD + lane * 4];
        const float4 q4 = *(const float4*)&q[(b * HQ + g * NREP + r) * HD + lane * 4];
        float ds = k4.x * q4.x + k4.y * q4.y + k4.z * q4.z + k4.w * q4.w;
#pragma unroll
        for (int off = 16; off; off >>= 1) ds += __shfl_xor_sync(0xffffffffu, ds, off);
        if (lane == 0) sn[r] = ds * scale;
    }
    __syncthreads();

    const int rr = t >> 7, d = t & 127;
    const float vnew = vn[(b * HKV + g) * HD + d];

    float mi[NSPLIT];
    float M = sn[rr];
#pragma unroll
    for (int i = 0; i < NSPLIT; i++) {
        mi[i] = pm[bg * (NSPLIT * NREP) + i * NREP + rr];
        M = fmaxf(M, mi[i]);
    }
    const float en = __expf(sn[rr] - M);
    float L = en;
    float num = en * vnew;
#pragma unroll
    for (int i = 0; i < NSPLIT; i++) {
        const float e = __expf(mi[i] - M);
        L += pl[bg * (NSPLIT * NREP) + i * NREP + rr] * e;
        num += pacc[((bg * NSPLIT + i) * NREP + rr) * HD + d] * e;
    }
    attn[(b * HQ + g * NREP + rr) * HD + d] = num / L;
}

// ------------------------------------------------------------------------------
// Final k-split reduce of wo GEMM partials -> d_out.  grid 512 x 256.
// ------------------------------------------------------------------------------
__global__ void final_reduce(const float* __restrict__ op, float* __restrict__ out)
{
    const int idx = blockIdx.x * 256 + threadIdx.x;  // < 131072
    float v = 0.f;
#pragma unroll
    for (int s = 0; s < KSPLIT; s++) v += op[s * NB * DIM + idx];
    out[idx] = v;
}

// ------------------------------------------------------------------------------
extern "C" void kernel_launch(void* const* d_in, const int* in_sizes, int n_in,
                              void* d_out, int out_size)
{
    const float* x  = (const float*)d_in[0];
    const float* ck = (const float*)d_in[1];
    const float* cv = (const float*)d_in[2];
    const float* wq = (const float*)d_in[3];
    const float* wk = (const float*)d_in[4];
    const float* wv = (const float*)d_in[5];
    const float* wo = (const float*)d_in[6];
    const float* fc = (const float*)d_in[7];
    const float* fs = (const float*)d_in[8];
    float* out = (float*)d_out;

    float *qkvp, *qb, *kn, *vn, *pm, *pl, *pacc, *attn, *op;
    cudaGetSymbolAddress((void**)&qkvp, g_qkvp);
    cudaGetSymbolAddress((void**)&qb,   g_q);
    cudaGetSymbolAddress((void**)&kn,   g_kn);
    cudaGetSymbolAddress((void**)&vn,   g_vn);
    cudaGetSymbolAddress((void**)&pm,   g_pm);
    cudaGetSymbolAddress((void**)&pl,   g_pl);
    cudaGetSymbolAddress((void**)&pacc, g_pacc);
    cudaGetSymbolAddress((void**)&attn, g_attn);
    cudaGetSymbolAddress((void**)&op,   g_op);

    // 1) fused QKV projection (k-split partials, f32x2)
    gemm_xwT<<<dim3(QKV_OUTS / 128, KSPLIT), 256>>>(x, wq, wk, wv, DIM, KVD, qkvp, QKV_OUTS);
    // 2) reduce partials + RoPE
    rope_reduce<<<384, 256>>>(qkvp, fc, fs, qb, kn, vn);
    // 3) split attention over cached tokens (pos 4095 masked)
    attn_split<<<dim3(NB * HKV, NSPLIT), 256>>>(qb, ck, cv, pm, pl, pacc);
    // 4) combine + new token
    attn_combine<<<NB * HKV, 512>>>(qb, kn, vn, pm, pl, pacc, attn);
    // 5) output projection (k-split partials, f32x2)
    gemm_xwT<<<dim3(DIM / 128, KSPLIT), 256>>>(attn, wo, wo, wo, DIM, 0, op, DIM);
    // 6) reduce to d_out
    final_reduce<<<512, 256>>>(op, out);
}

// round 3
// speedup vs baseline: 1.4201x; 1.0263x over previous
#include <cuda_runtime.h>
#include <cuda_bf16.h>
#include <math.h>

// Problem constants
#define NB     32      // batch
#define HQ     32
#define HKV    8
#define NREP   4
#define HD     128
#define DIM    4096    // HQ*HD
#define KVD    1024    // HKV*HD
#define MAXSEQ 4096
#define NEWPOS 4095

#define KSPLIT 16      // GEMM k-split
#define KB     256     // 4096 / KSPLIT
#define QKV_OUTS 6144  // 4096 + 1024 + 1024
#define NSPLIT 16      // attention seq splits
#define SCHUNK 256     // 4096 / 16

// ---------------- scratch (device globals; no allocations allowed) -------------
__device__ float g_qkvp[KSPLIT * NB * QKV_OUTS];   // qkv gemm partials (12.6MB)
__device__ float g_q   [NB * DIM];                  // rope'd q
__device__ float g_kn  [NB * KVD];                  // rope'd new k
__device__ float g_vn  [NB * KVD];                  // new v
__device__ float g_pm  [NB * HKV * NSPLIT * NREP];  // partial max
__device__ float g_pl  [NB * HKV * NSPLIT * NREP];  // partial sum
__device__ float g_pacc[NB * HKV * NSPLIT * NREP * HD]; // partial acc (8.4MB)
__device__ float g_attn[NB * DIM];                  // attention output
__device__ float g_op  [KSPLIT * NB * DIM];         // wo gemm partials (8MB)

// ---------------- f32x2 helpers -------------------------------------------------
__device__ __forceinline__ unsigned long long f2fma(unsigned long long a,
                                                    unsigned long long b,
                                                    unsigned long long c) {
    unsigned long long d;
    asm("fma.rn.f32x2 %0, %1, %2, %3;" : "=l"(d) : "l"(a), "l"(b), "l"(c));
    return d;
}
__device__ __forceinline__ float2 uf2(unsigned long long u) {
    float2 f;
    asm("mov.b64 {%0, %1}, %2;" : "=f"(f.x), "=f"(f.y) : "l"(u));
    return f;
}
__device__ __forceinline__ unsigned long long dupf(float p) {
    unsigned long long u;
    asm("mov.b64 %0, {%1, %1};" : "=l"(u) : "f"(p));
    return u;
}

// ------------------------------------------------------------------------------
// GEMM v3: y[b,o] = sum_k x[b,k] * W[o,k].  f32x2, thread tile 8 outs x 8 b.
// grid: (OUTS/256, KSPLIT), 128 threads (4 warps).
// Block tile: 256 outs x 32 b x 256 k. Thread outs: {lane*4..+3} U {128+lane*4..+3};
// batches: warp*8..+7. Per kk: 2 conflict-free LDS128 (w pairs) + 8 broadcast
// LDS64 (x dup) = 16 smem phases per 32 f32x2 -> crossbar:fma = 1:1.
// ------------------------------------------------------------------------------
__global__ __launch_bounds__(128)
void gemm_xwT(const float* __restrict__ x,
              const float* __restrict__ w0,
              const float* __restrict__ w1,
              const float* __restrict__ w2,
              int n0, int n1,
              float* __restrict__ yp, int OUTS)
{
    const int obase = blockIdx.x * 256;
    const float* wp;
    int orow;
    if (obase < n0)            { wp = w0; orow = obase; }
    else if (obase < n0 + n1)  { wp = w1; orow = obase - n0; }
    else                       { wp = w2; orow = obase - n0 - n1; }
    const int kb0 = blockIdx.y * KB;

    __shared__ __align__(16) float ws[16 * 264];   // [k][o:256 + pad]
    __shared__ __align__(16) float xs2[16 * 68];   // [k][b dup pairs]

    const int t    = threadIdx.x;
    const int lane = t & 31;
    const int w    = t >> 5;

    // load indices
    const int lxb = t >> 2;          // x: batch row
    const int lxk = (t & 3) * 4;     // x: k offset

    unsigned long long acc2[4][8];   // [o-pair][batch]
#pragma unroll
    for (int p = 0; p < 4; p++)
#pragma unroll
        for (int i = 0; i < 8; i++) acc2[p][i] = 0ull;

    for (int kt = 0; kt < KB / 16; kt++) {
        const int kbase = kb0 + kt * 16;

        // stage loads in registers: thread owns w rows o=t and o=t+128, 4xfloat4 each
        float4 wv[8];
#pragma unroll
        for (int h = 0; h < 2; h++)
#pragma unroll
            for (int q = 0; q < 4; q++)
                wv[h * 4 + q] = *(const float4*)&wp[(orow + t + h * 128) * 4096 + kbase + q * 4];
        float4 xv = *(const float4*)&x[lxb * 4096 + kbase + lxk];

        __syncthreads();   // previous tile's compute done
#pragma unroll
        for (int h = 0; h < 2; h++) {
            const int o = t + h * 128;
#pragma unroll
            for (int q = 0; q < 4; q++) {
                ws[(q * 4 + 0) * 264 + o] = wv[h * 4 + q].x;
                ws[(q * 4 + 1) * 264 + o] = wv[h * 4 + q].y;
                ws[(q * 4 + 2) * 264 + o] = wv[h * 4 + q].z;
                ws[(q * 4 + 3) * 264 + o] = wv[h * 4 + q].w;
            }
        }
        xs2[(lxk + 0) * 68 + lxb * 2] = xv.x; xs2[(lxk + 0) * 68 + lxb * 2 + 1] = xv.x;
        xs2[(lxk + 1) * 68 + lxb * 2] = xv.y; xs2[(lxk + 1) * 68 + lxb * 2 + 1] = xv.y;
        xs2[(lxk + 2) * 68 + lxb * 2] = xv.z; xs2[(lxk + 2) * 68 + lxb * 2 + 1] = xv.z;
        xs2[(lxk + 3) * 68 + lxb * 2] = xv.w; xs2[(lxk + 3) * 68 + lxb * 2 + 1] = xv.w;
        __syncthreads();

#pragma unroll
        for (int kk = 0; kk < 16; kk++) {
            const ulonglong2 wA = *(const ulonglong2*)&ws[kk * 264 + lane * 4];
            const ulonglong2 wB = *(const ulonglong2*)&ws[kk * 264 + 128 + lane * 4];
#pragma unroll
            for (int i = 0; i < 8; i++) {
                const unsigned long long xp = *(const unsigned long long*)&xs2[kk * 68 + (w * 8 + i) * 2];
                acc2[0][i] = f2fma(wA.x, xp, acc2[0][i]);
                acc2[1][i] = f2fma(wA.y, xp, acc2[1][i]);
                acc2[2][i] = f2fma(wB.x, xp, acc2[2][i]);
                acc2[3][i] = f2fma(wB.y, xp, acc2[3][i]);
            }
        }
    }

#pragma unroll
    for (int p = 0; p < 4; p++) {
        const int o = obase + ((p < 2) ? 0 : 128) + lane * 4 + (p & 1) * 2;
#pragma unroll
        for (int i = 0; i < 8; i++) {
            const int b = w * 8 + i;
            float2 f = uf2(acc2[p][i]);
            *(float2*)&yp[(blockIdx.y * NB + b) * OUTS + o] = f;
        }
    }
}

// ------------------------------------------------------------------------------
// RoPE + k-split reduce. grid 384 x 256.
// ------------------------------------------------------------------------------
__global__ void rope_reduce(const float* __restrict__ qkvp,
                            const float* __restrict__ fc,
                            const float* __restrict__ fs,
                            float* __restrict__ qout,
                            float* __restrict__ kout,
                            float* __restrict__ vout)
{
    const int idx = blockIdx.x * 256 + threadIdx.x;  // < 98304
    const int b  = idx / 3072;
    const int jp = idx % 3072;
    const int j0 = jp * 2;

    float v0 = 0.f, v1 = 0.f;
#pragma unroll
    for (int s = 0; s < KSPLIT; s++) {
        const float* p = qkvp + (s * NB + b) * QKV_OUTS + j0;
        v0 += p[0];
        v1 += p[1];
    }
    if (j0 < DIM + KVD) {
        const int i = jp & 63;
        const float c = fc[i], s_ = fs[i];
        const float re = v0 * c - v1 * s_;
        const float im = v0 * s_ + v1 * c;
        v0 = re; v1 = im;
    }
    if (j0 < DIM) {
        qout[b * DIM + j0] = v0;
        qout[b * DIM + j0 + 1] = v1;
    } else if (j0 < DIM + KVD) {
        kout[b * KVD + (j0 - DIM)] = v0;
        kout[b * KVD + (j0 - DIM) + 1] = v1;
    } else {
        vout[b * KVD + (j0 - DIM - KVD)] = v0;
        vout[b * KVD + (j0 - DIM - KVD) + 1] = v1;
    }
}

// ------------------------------------------------------------------------------
// Flash-decode split attention v3. grid (256, 16), 256 threads. SCHUNK=256.
// Non-duplicated prob smem (pairs packed via mov.b64 in PV). smem ~27KB.
// ------------------------------------------------------------------------------
__global__ __launch_bounds__(256)
void attn_split(const float* __restrict__ q,
                const float* __restrict__ ck,
                const float* __restrict__ cv,
                float* __restrict__ pm,
                float* __restrict__ pl,
                float* __restrict__ pacc)
{
    const int bg = blockIdx.x;
    const int b = bg >> 3, g = bg & 7;
    const int split = blockIdx.y;
    const int t = threadIdx.x;
    const int lane = t & 31, w = t >> 5;
    const int sbase = split * SCHUNK;

    __shared__ __align__(16) float sm[6788];
    float* qs   = sm;            // [4][128]            (512)
    float* ks   = sm + 512;      // [32][132]           (4224)  aliased by pvpart [8][4][128]
    float* sc   = sm + 4736;     // [4][256]            (1024)
    float* part = sm + 5760;     // [8][4][32]          (1024)
    float* mf   = sm + 6784;     // [4]

    const float scale = 0.08838834764831845f;  // 1/sqrt(128)

    // q staging (pre-scaled)
    for (int i = t; i < 512; i += 256) {
        const int r = i >> 7, d = i & 127;
        qs[r * 128 + d] = q[(b * HQ + g * NREP + r) * HD + d] * scale;
    }

    float mloc = -1e30f;
    const int s_loc = t & 31;
    const int dg = t >> 5;
    const int base_d = dg * 16;

    for (int tile = 0; tile < SCHUNK / 32; tile++) {
        __syncthreads();
        // stage K[32][128] coalesced
#pragma unroll
        for (int i = 0; i < 4; i++) {
            const int f4 = t + i * 256;
            const int row = f4 >> 5, c4 = (f4 & 31) * 4;
            float4 kv = *(const float4*)&ck[(size_t)(b * MAXSEQ + sbase + tile * 32 + row) * KVD + g * HD + c4];
            *(float4*)&ks[row * 132 + c4] = kv;
        }
        __syncthreads();

        unsigned long long racc[4] = {0ull, 0ull, 0ull, 0ull};
#pragma unroll
        for (int c = 0; c < 4; c++) {
            ulonglong2 kk = *(const ulonglong2*)&ks[s_loc * 132 + base_d + c * 4];
#pragma unroll
            for (int r = 0; r < 4; r++) {
                ulonglong2 qq = *(const ulonglong2*)&qs[r * 128 + base_d + c * 4];
                racc[r] = f2fma(kk.x, qq.x, racc[r]);
                racc[r] = f2fma(kk.y, qq.y, racc[r]);
            }
        }
#pragma unroll
        for (int r = 0; r < 4; r++) {
            float2 f = uf2(racc[r]);
            part[(dg * 4 + r) * 32 + s_loc] = f.x + f.y;
        }
        __syncthreads();
        if (t < 128) {
            const int r = t >> 5;
            float val = 0.f;
#pragma unroll
            for (int d8 = 0; d8 < 8; d8++) val += part[(d8 * 4 + r) * 32 + lane];
            const int sg = sbase + tile * 32 + lane;
            if (sg == NEWPOS) val = -1e30f;
            sc[r * SCHUNK + tile * 32 + lane] = val;
            mloc = fmaxf(mloc, val);
        }
    }

    // per-rep max
    if (t < 128) {
#pragma unroll
        for (int off = 16; off; off >>= 1)
            mloc = fmaxf(mloc, __shfl_xor_sync(0xffffffffu, mloc, off));
        if (lane == 0) mf[t >> 5] = mloc;
    }
    __syncthreads();

    // exp + row sums
    {
        const int r = t >> 6, s0 = t & 63;
        const float m = mf[r];
        float ls = 0.f;
#pragma unroll
        for (int j = 0; j < SCHUNK / 64; j++) {
            const int sl = s0 + j * 64;
            const float p = __expf(sc[r * SCHUNK + sl] - m);
            sc[r * SCHUNK + sl] = p;
            ls += p;
        }
#pragma unroll
        for (int off = 16; off; off >>= 1)
            ls += __shfl_xor_sync(0xffffffffu, ls, off);
        if (lane == 0) part[w] = ls;
    }
    __syncthreads();
    if (t < 4) {
        pm[bg * (NSPLIT * NREP) + split * NREP + t] = mf[t];
        pl[bg * (NSPLIT * NREP) + split * NREP + t] = part[2 * t] + part[2 * t + 1];
    }

    // P @ V : thread = (d-quarter, s-group of 32)
    float* pvp = ks;   // alias, [8][4][128]
    {
        const int dq = lane;     // d = dq*4 .. +3
        const int sg8 = w;       // s-group
        unsigned long long a[4][2];
#pragma unroll
        for (int r = 0; r < 4; r++) { a[r][0] = 0ull; a[r][1] = 0ull; }
        for (int i = 0; i < SCHUNK / 8; i++) {
            const int sl = sg8 * (SCHUNK / 8) + i;
            const int s = sbase + sl;
            ulonglong2 vv = *(const ulonglong2*)&cv[(size_t)(b * MAXSEQ + s) * KVD + g * HD + dq * 4];
#pragma unroll
            for (int r = 0; r < 4; r++) {
                const unsigned long long pp = dupf(sc[r * SCHUNK + sl]);
                a[r][0] = f2fma(pp, vv.x, a[r][0]);
                a[r][1] = f2fma(pp, vv.y, a[r][1]);
            }
        }
#pragma unroll
        for (int r = 0; r < 4; r++) {
            float2 f0 = uf2(a[r][0]), f1 = uf2(a[r][1]);
            float4 o4 = make_float4(f0.x, f0.y, f1.x, f1.y);
            *(float4*)&pvp[(sg8 * 4 + r) * 128 + dq * 4] = o4;
        }
    }
    __syncthreads();
#pragma unroll
    for (int i = 0; i < 2; i++) {
        const int idx = t + i * 256;   // 512 outputs
        const int r = idx >> 7, d = idx & 127;
        float v = 0.f;
#pragma unroll
        for (int sgp = 0; sgp < 8; sgp++) v += pvp[(sgp * 4 + r) * 128 + d];
        pacc[((bg * NSPLIT + split) * NREP + r) * HD + d] = v;
    }
}

// ------------------------------------------------------------------------------
// Combine partials + new token (s=4095). grid 256, 512 threads: t -> (rep, d).
// ------------------------------------------------------------------------------
__global__ __launch_bounds__(512)
void attn_combine(const float* __restrict__ q,
                  const float* __restrict__ kn,
                  const float* __restrict__ vn,
                  const float* __restrict__ pm,
                  const float* __restrict__ pl,
                  const float* __restrict__ pacc,
                  float* __restrict__ attn)
{
    const int bg = blockIdx.x;
    const int b = bg >> 3, g = bg & 7;
    const int t = threadIdx.x, lane = t & 31;
    __shared__ float sn[4];
    const float scale = 0.08838834764831845f;

    if (t < 128) {
        const int r = t >> 5;
        const float4 k4 = *(const float4*)&kn[(b * HKV + g) * HD + lane * 4];
        const float4 q4 = *(const float4*)&q[(b * HQ + g * NREP + r) * HD + lane * 4];
        float ds = k4.x * q4.x + k4.y * q4.y + k4.z * q4.z + k4.w * q4.w;
#pragma unroll
        for (int off = 16; off; off >>= 1) ds += __shfl_xor_sync(0xffffffffu, ds, off);
        if (lane == 0) sn[r] = ds * scale;
    }
    __syncthreads();

    const int rr = t >> 7, d = t & 127;
    const float vnew = vn[(b * HKV + g) * HD + d];

    float mi[NSPLIT];
    float M = sn[rr];
#pragma unroll
    for (int i = 0; i < NSPLIT; i++) {
        mi[i] = pm[bg * (NSPLIT * NREP) + i * NREP + rr];
        M = fmaxf(M, mi[i]);
    }
    const float en = __expf(sn[rr] - M);
    float L = en;
    float num = en * vnew;
#pragma unroll
    for (int i = 0; i < NSPLIT; i++) {
        const float e = __expf(mi[i] - M);
        L += pl[bg * (NSPLIT * NREP) + i * NREP + rr] * e;
        num += pacc[((bg * NSPLIT + i) * NREP + rr) * HD + d] * e;
    }
    attn[(b * HQ + g * NREP + rr) * HD + d] = num / L;
}

// ------------------------------------------------------------------------------
// Final k-split reduce of wo GEMM partials -> d_out.  grid 512 x 256.
// ------------------------------------------------------------------------------
__global__ void final_reduce(const float* __restrict__ op, float* __restrict__ out)
{
    const int idx = blockIdx.x * 256 + threadIdx.x;  // < 131072
    float v = 0.f;
#pragma unroll
    for (int s = 0; s < KSPLIT; s++) v += op[s * NB * DIM + idx];
    out[idx] = v;
}

// ------------------------------------------------------------------------------
extern "C" void kernel_launch(void* const* d_in, const int* in_sizes, int n_in,
                              void* d_out, int out_size)
{
    const float* x  = (const float*)d_in[0];
    const float* ck = (const float*)d_in[1];
    const float* cv = (const float*)d_in[2];
    const float* wq = (const float*)d_in[3];
    const float* wk = (const float*)d_in[4];
    const float* wv = (const float*)d_in[5];
    const float* wo = (const float*)d_in[6];
    const float* fc = (const float*)d_in[7];
    const float* fs = (const float*)d_in[8];
    float* out = (float*)d_out;

    float *qkvp, *qb, *kn, *vn, *pm, *pl, *pacc, *attn, *op;
    cudaGetSymbolAddress((void**)&qkvp, g_qkvp);
    cudaGetSymbolAddress((void**)&qb,   g_q);
    cudaGetSymbolAddress((void**)&kn,   g_kn);
    cudaGetSymbolAddress((void**)&vn,   g_vn);
    cudaGetSymbolAddress((void**)&pm,   g_pm);
    cudaGetSymbolAddress((void**)&pl,   g_pl);
    cudaGetSymbolAddress((void**)&pacc, g_pacc);
    cudaGetSymbolAddress((void**)&attn, g_attn);
    cudaGetSymbolAddress((void**)&op,   g_op);

    // 1) fused QKV projection (k-split partials, f32x2, 8x8 tiles)
    gemm_xwT<<<dim3(QKV_OUTS / 256, KSPLIT), 128>>>(x, wq, wk, wv, DIM, KVD, qkvp, QKV_OUTS);
    // 2) reduce partials + RoPE
    rope_reduce<<<384, 256>>>(qkvp, fc, fs, qb, kn, vn);
    // 3) split attention over cached tokens (pos 4095 masked)
    attn_split<<<dim3(NB * HKV, NSPLIT), 256>>>(qb, ck, cv, pm, pl, pacc);
    // 4) combine + new token
    attn_combine<<<NB * HKV, 512>>>(qb, kn, vn, pm, pl, pacc, attn);
    // 5) output projection (k-split partials, f32x2, 8x8 tiles)
    gemm_xwT<<<dim3(DIM / 256, KSPLIT), 128>>>(attn, wo, wo, wo, DIM, 0, op, DIM);
    // 6) reduce to d_out
    final_reduce<<<512, 256>>>(op, out);
}

// round 4
// speedup vs baseline: 1.4474x; 1.0192x over previous
#include <cuda_runtime.h>
#include <cuda_bf16.h>
#include <math.h>

// Problem constants
#define NB     32      // batch
#define HQ     32
#define HKV    8
#define NREP   4
#define HD     128
#define DIM    4096    // HQ*HD
#define KVD    1024    // HKV*HD
#define MAXSEQ 4096
#define NEWPOS 4095

#define KSPLIT 32      // GEMM k-split
#define KB     128     // 4096 / KSPLIT
#define QKV_OUTS 6144  // 4096 + 1024 + 1024
#define NSPLIT 16      // attention seq splits
#define SCHUNK 256     // 4096 / 16

// ---------------- scratch (device globals; no allocations allowed) -------------
__device__ float g_qkvp[KSPLIT * NB * QKV_OUTS];   // qkv gemm partials (25.2MB)
__device__ float g_q   [NB * DIM];                  // rope'd q
__device__ float g_kn  [NB * KVD];                  // rope'd new k
__device__ float g_vn  [NB * KVD];                  // new v
__device__ float g_pm  [NB * HKV * NSPLIT * NREP];  // partial max
__device__ float g_pl  [NB * HKV * NSPLIT * NREP];  // partial sum
__device__ float g_pacc[NB * HKV * NSPLIT * NREP * HD]; // partial acc (8.4MB)
__device__ float g_attn[NB * DIM];                  // attention output
__device__ float g_op  [KSPLIT * NB * DIM];         // wo gemm partials (16.8MB)

// ---------------- f32x2 helpers -------------------------------------------------
__device__ __forceinline__ unsigned long long f2fma(unsigned long long a,
                                                    unsigned long long b,
                                                    unsigned long long c) {
    unsigned long long d;
    asm("fma.rn.f32x2 %0, %1, %2, %3;" : "=l"(d) : "l"(a), "l"(b), "l"(c));
    return d;
}
__device__ __forceinline__ float2 uf2(unsigned long long u) {
    float2 f;
    asm("mov.b64 {%0, %1}, %2;" : "=f"(f.x), "=f"(f.y) : "l"(u));
    return f;
}
__device__ __forceinline__ unsigned long long dupf(float p) {
    unsigned long long u;
    asm("mov.b64 %0, {%1, %1};" : "=l"(u) : "f"(p));
    return u;
}

// ------------------------------------------------------------------------------
// GEMM v4: y[b,o] = sum_k x[b,k] * W[o,k].  f32x2, thread tile 8 outs x 8 b.
// grid: (OUTS/256, KSPLIT), 128 threads. Software-pipelined: next k-tile's LDGs
// are issued after this tile's STS/sync, overlapping the compute phase.
// ------------------------------------------------------------------------------
__global__ __launch_bounds__(128)
void gemm_xwT(const float* __restrict__ x,
              const float* __restrict__ w0,
              const float* __restrict__ w1,
              const float* __restrict__ w2,
              int n0, int n1,
              float* __restrict__ yp, int OUTS)
{
    const int obase = blockIdx.x * 256;
    const float* wp;
    int orow;
    if (obase < n0)            { wp = w0; orow = obase; }
    else if (obase < n0 + n1)  { wp = w1; orow = obase - n0; }
    else                       { wp = w2; orow = obase - n0 - n1; }
    const int kb0 = blockIdx.y * KB;

    __shared__ __align__(16) float ws[16 * 264];   // [k][o:256 + pad]
    __shared__ __align__(16) float xs2[16 * 68];   // [k][b dup pairs]

    const int t    = threadIdx.x;
    const int lane = t & 31;
    const int w    = t >> 5;

    const int lxb = t >> 2;          // x: batch row
    const int lxk = (t & 3) * 4;     // x: k offset

    unsigned long long acc2[4][8];   // [o-pair][batch]
#pragma unroll
    for (int p = 0; p < 4; p++)
#pragma unroll
        for (int i = 0; i < 8; i++) acc2[p][i] = 0ull;

    const int NT = KB / 16;

    // prologue: load tile 0
    float4 wv[8], xv;
#pragma unroll
    for (int h = 0; h < 2; h++)
#pragma unroll
        for (int q = 0; q < 4; q++)
            wv[h * 4 + q] = *(const float4*)&wp[(orow + t + h * 128) * 4096 + kb0 + q * 4];
    xv = *(const float4*)&x[lxb * 4096 + kb0 + lxk];

    for (int kt = 0; kt < NT; kt++) {
        __syncthreads();   // smem free (prev compute done)
#pragma unroll
        for (int h = 0; h < 2; h++) {
            const int o = t + h * 128;
#pragma unroll
            for (int q = 0; q < 4; q++) {
                ws[(q * 4 + 0) * 264 + o] = wv[h * 4 + q].x;
                ws[(q * 4 + 1) * 264 + o] = wv[h * 4 + q].y;
                ws[(q * 4 + 2) * 264 + o] = wv[h * 4 + q].z;
                ws[(q * 4 + 3) * 264 + o] = wv[h * 4 + q].w;
            }
        }
        xs2[(lxk + 0) * 68 + lxb * 2] = xv.x; xs2[(lxk + 0) * 68 + lxb * 2 + 1] = xv.x;
        xs2[(lxk + 1) * 68 + lxb * 2] = xv.y; xs2[(lxk + 1) * 68 + lxb * 2 + 1] = xv.y;
        xs2[(lxk + 2) * 68 + lxb * 2] = xv.z; xs2[(lxk + 2) * 68 + lxb * 2 + 1] = xv.z;
        xs2[(lxk + 3) * 68 + lxb * 2] = xv.w; xs2[(lxk + 3) * 68 + lxb * 2 + 1] = xv.w;
        __syncthreads();

        // issue next tile's loads (overlap with compute below)
        if (kt + 1 < NT) {
            const int kbase = kb0 + (kt + 1) * 16;
#pragma unroll
            for (int h = 0; h < 2; h++)
#pragma unroll
                for (int q = 0; q < 4; q++)
                    wv[h * 4 + q] = *(const float4*)&wp[(orow + t + h * 128) * 4096 + kbase + q * 4];
            xv = *(const float4*)&x[lxb * 4096 + kbase + lxk];
        }

#pragma unroll
        for (int kk = 0; kk < 16; kk++) {
            const ulonglong2 wA = *(const ulonglong2*)&ws[kk * 264 + lane * 4];
            const ulonglong2 wB = *(const ulonglong2*)&ws[kk * 264 + 128 + lane * 4];
#pragma unroll
            for (int i = 0; i < 8; i++) {
                const unsigned long long xp = *(const unsigned long long*)&xs2[kk * 68 + (w * 8 + i) * 2];
                acc2[0][i] = f2fma(wA.x, xp, acc2[0][i]);
                acc2[1][i] = f2fma(wA.y, xp, acc2[1][i]);
                acc2[2][i] = f2fma(wB.x, xp, acc2[2][i]);
                acc2[3][i] = f2fma(wB.y, xp, acc2[3][i]);
            }
        }
    }

#pragma unroll
    for (int p = 0; p < 4; p++) {
        const int o = obase + ((p < 2) ? 0 : 128) + lane * 4 + (p & 1) * 2;
#pragma unroll
        for (int i = 0; i < 8; i++) {
            const int b = w * 8 + i;
            float2 f = uf2(acc2[p][i]);
            *(float2*)&yp[(blockIdx.y * NB + b) * OUTS + o] = f;
        }
    }
}

// ------------------------------------------------------------------------------
// RoPE + k-split reduce. grid 384 x 256.
// ------------------------------------------------------------------------------
__global__ void rope_reduce(const float* __restrict__ qkvp,
                            const float* __restrict__ fc,
                            const float* __restrict__ fs,
                            float* __restrict__ qout,
                            float* __restrict__ kout,
                            float* __restrict__ vout)
{
    const int idx = blockIdx.x * 256 + threadIdx.x;  // < 98304
    const int b  = idx / 3072;
    const int jp = idx % 3072;
    const int j0 = jp * 2;

    float v0 = 0.f, v1 = 0.f;
#pragma unroll
    for (int s = 0; s < KSPLIT; s++) {
        const float* p = qkvp + (s * NB + b) * QKV_OUTS + j0;
        v0 += p[0];
        v1 += p[1];
    }
    if (j0 < DIM + KVD) {
        const int i = jp & 63;
        const float c = fc[i], s_ = fs[i];
        const float re = v0 * c - v1 * s_;
        const float im = v0 * s_ + v1 * c;
        v0 = re; v1 = im;
    }
    if (j0 < DIM) {
        qout[b * DIM + j0] = v0;
        qout[b * DIM + j0 + 1] = v1;
    } else if (j0 < DIM + KVD) {
        kout[b * KVD + (j0 - DIM)] = v0;
        kout[b * KVD + (j0 - DIM) + 1] = v1;
    } else {
        vout[b * KVD + (j0 - DIM - KVD)] = v0;
        vout[b * KVD + (j0 - DIM - KVD) + 1] = v1;
    }
}

// ------------------------------------------------------------------------------
// Flash-decode split attention v4. grid (256, 16), 256 threads.
// QK phase software-pipelined (double-buffered K smem; next tile's LDGs issued
// before this tile's compute). PV loads unrolled x4 for MLP. 2 barriers/tile.
// ------------------------------------------------------------------------------
__global__ __launch_bounds__(256)
void attn_split(const float* __restrict__ q,
                const float* __restrict__ ck,
                const float* __restrict__ cv,
                float* __restrict__ pm,
                float* __restrict__ pl,
                float* __restrict__ pacc)
{
    const int bg = blockIdx.x;
    const int b = bg >> 3, g = bg & 7;
    const int split = blockIdx.y;
    const int t = threadIdx.x;
    const int lane = t & 31, w = t >> 5;
    const int sbase = split * SCHUNK;

    __shared__ __align__(16) float sm[11012];
    float* qs   = sm;             // [4][128]             512
    float* kbuf = sm + 512;       // 2 x [32][132]        8448  (aliased by pvp)
    float* sc   = sm + 8960;      // [4][256]             1024
    float* part = sm + 9984;      // [8][4][32]           1024
    float* mf   = sm + 11008;     // [4]
    float* pvp  = kbuf;           // alias, [8][4][128] = 4096

    const float scale = 0.08838834764831845f;  // 1/sqrt(128)

    // q staging (pre-scaled)
    for (int i = t; i < 512; i += 256) {
        const int r = i >> 7, d = i & 127;
        qs[r * 128 + d] = q[(b * HQ + g * NREP + r) * HD + d] * scale;
    }

    const int s_loc = t & 31;
    const int dg = t >> 5;
    const int base_d = dg * 16;
    const size_t ckb = (size_t)(b * MAXSEQ) * KVD + g * HD;

    // staging geometry: i in 0..3 -> f4 = t + i*256, row = f4>>5, c4 = (f4&31)*4
    float4 kreg[4];
#pragma unroll
    for (int i = 0; i < 4; i++) {
        const int f4 = t + i * 256;
        const int row = f4 >> 5, c4 = (f4 & 31) * 4;
        kreg[i] = *(const float4*)&ck[ckb + (size_t)(sbase + row) * KVD + c4];
    }

    float mloc = -1e30f;

    for (int tile = 0; tile < SCHUNK / 32; tile++) {
        float* kb = kbuf + (tile & 1) * 4224;
#pragma unroll
        for (int i = 0; i < 4; i++) {
            const int f4 = t + i * 256;
            const int row = f4 >> 5, c4 = (f4 & 31) * 4;
            *(float4*)&kb[row * 132 + c4] = kreg[i];
        }
        __syncthreads();   // kb ready (also covers qs on tile 0)

        // prefetch next tile (overlaps compute + reduce)
        if (tile + 1 < SCHUNK / 32) {
#pragma unroll
            for (int i = 0; i < 4; i++) {
                const int f4 = t + i * 256;
                const int row = f4 >> 5, c4 = (f4 & 31) * 4;
                kreg[i] = *(const float4*)&ck[ckb + (size_t)(sbase + (tile + 1) * 32 + row) * KVD + c4];
            }
        }

        unsigned long long racc[4] = {0ull, 0ull, 0ull, 0ull};
#pragma unroll
        for (int c = 0; c < 4; c++) {
            ulonglong2 kk = *(const ulonglong2*)&kb[s_loc * 132 + base_d + c * 4];
#pragma unroll
            for (int r = 0; r < 4; r++) {
                ulonglong2 qq = *(const ulonglong2*)&qs[r * 128 + base_d + c * 4];
                racc[r] = f2fma(kk.x, qq.x, racc[r]);
                racc[r] = f2fma(kk.y, qq.y, racc[r]);
            }
        }
#pragma unroll
        for (int r = 0; r < 4; r++) {
            float2 f = uf2(racc[r]);
            part[(dg * 4 + r) * 32 + s_loc] = f.x + f.y;
        }
        __syncthreads();   // part ready
        if (t < 128) {
            const int r = t >> 5;
            float val = 0.f;
#pragma unroll
            for (int d8 = 0; d8 < 8; d8++) val += part[(d8 * 4 + r) * 32 + lane];
            const int sg = sbase + tile * 32 + lane;
            if (sg == NEWPOS) val = -1e30f;
            sc[r * SCHUNK + tile * 32 + lane] = val;
            mloc = fmaxf(mloc, val);
        }
    }

    // per-rep max
    if (t < 128) {
#pragma unroll
        for (int off = 16; off; off >>= 1)
            mloc = fmaxf(mloc, __shfl_xor_sync(0xffffffffu, mloc, off));
        if (lane == 0) mf[t >> 5] = mloc;
    }
    __syncthreads();

    // exp + row sums
    {
        const int r = t >> 6, s0 = t & 63;
        const float m = mf[r];
        float ls = 0.f;
#pragma unroll
        for (int j = 0; j < SCHUNK / 64; j++) {
            const int sl = s0 + j * 64;
            const float p = __expf(sc[r * SCHUNK + sl] - m);
            sc[r * SCHUNK + sl] = p;
            ls += p;
        }
#pragma unroll
        for (int off = 16; off; off >>= 1)
            ls += __shfl_xor_sync(0xffffffffu, ls, off);
        if (lane == 0) part[w] = ls;
    }
    __syncthreads();
    if (t < 4) {
        pm[bg * (NSPLIT * NREP) + split * NREP + t] = mf[t];
        pl[bg * (NSPLIT * NREP) + split * NREP + t] = part[2 * t] + part[2 * t + 1];
    }

    // P @ V : thread = (d-quarter, s-group of 32), loads unrolled x4
    {
        const int dq = lane;
        const int sg8 = w;
        const size_t cvb = (size_t)(b * MAXSEQ) * KVD + g * HD + dq * 4;
        unsigned long long a[4][2];
#pragma unroll
        for (int r = 0; r < 4; r++) { a[r][0] = 0ull; a[r][1] = 0ull; }
        for (int i0 = 0; i0 < 32; i0 += 4) {
            ulonglong2 vv[4];
#pragma unroll
            for (int j = 0; j < 4; j++) {
                const int sl = sg8 * 32 + i0 + j;
                vv[j] = *(const ulonglong2*)&cv[cvb + (size_t)(sbase + sl) * KVD];
            }
#pragma unroll
            for (int j = 0; j < 4; j++) {
                const int sl = sg8 * 32 + i0 + j;
#pragma unroll
                for (int r = 0; r < 4; r++) {
                    const unsigned long long pp = dupf(sc[r * SCHUNK + sl]);
                    a[r][0] = f2fma(pp, vv[j].x, a[r][0]);
                    a[r][1] = f2fma(pp, vv[j].y, a[r][1]);
                }
            }
        }
#pragma unroll
        for (int r = 0; r < 4; r++) {
            float2 f0 = uf2(a[r][0]), f1 = uf2(a[r][1]);
            float4 o4 = make_float4(f0.x, f0.y, f1.x, f1.y);
            *(float4*)&pvp[(sg8 * 4 + r) * 128 + dq * 4] = o4;
        }
    }
    __syncthreads();
#pragma unroll
    for (int i = 0; i < 2; i++) {
        const int idx = t + i * 256;   // 512 outputs
        const int r = idx >> 7, d = idx & 127;
        float v = 0.f;
#pragma unroll
        for (int sgp = 0; sgp < 8; sgp++) v += pvp[(sgp * 4 + r) * 128 + d];
        pacc[((bg * NSPLIT + split) * NREP + r) * HD + d] = v;
    }
}

// ------------------------------------------------------------------------------
// Combine partials + new token (s=4095). grid (256, 4), 128 threads.
// ------------------------------------------------------------------------------
__global__ __launch_bounds__(128)
void attn_combine(const float* __restrict__ q,
                  const float* __restrict__ kn,
                  const float* __restrict__ vn,
                  const float* __restrict__ pm,
                  const float* __restrict__ pl,
                  const float* __restrict__ pacc,
                  float* __restrict__ attn)
{
    const int bg = blockIdx.x;
    const int b = bg >> 3, g = bg & 7;
    const int rr = blockIdx.y;
    const int t = threadIdx.x, lane = t & 31;
    __shared__ float sn1;
    const float scale = 0.08838834764831845f;

    if (t < 32) {
        const float4 k4 = *(const float4*)&kn[(b * HKV + g) * HD + lane * 4];
        const float4 q4 = *(const float4*)&q[(b * HQ + g * NREP + rr) * HD + lane * 4];
        float ds = k4.x * q4.x + k4.y * q4.y + k4.z * q4.z + k4.w * q4.w;
#pragma unroll
        for (int off = 16; off; off >>= 1) ds += __shfl_xor_sync(0xffffffffu, ds, off);
        if (lane == 0) sn1 = ds * scale;
    }
    __syncthreads();

    const int d = t;
    const float vnew = vn[(b * HKV + g) * HD + d];

    float mi[NSPLIT];
    float M = sn1;
#pragma unroll
    for (int i = 0; i < NSPLIT; i++) {
        mi[i] = pm[bg * (NSPLIT * NREP) + i * NREP + rr];
        M = fmaxf(M, mi[i]);
    }
    const float en = __expf(sn1 - M);
    float L = en;
    float num = en * vnew;
#pragma unroll
    for (int i = 0; i < NSPLIT; i++) {
        const float e = __expf(mi[i] - M);
        L += pl[bg * (NSPLIT * NREP) + i * NREP + rr] * e;
        num += pacc[((bg * NSPLIT + i) * NREP + rr) * HD + d] * e;
    }
    attn[(b * HQ + g * NREP + rr) * HD + d] = num / L;
}

// ------------------------------------------------------------------------------
// Final k-split reduce of wo GEMM partials -> d_out.  grid 512 x 256.
// ------------------------------------------------------------------------------
__global__ void final_reduce(const float* __restrict__ op, float* __restrict__ out)
{
    const int idx = blockIdx.x * 256 + threadIdx.x;  // < 131072
    float v = 0.f;
#pragma unroll
    for (int s = 0; s < KSPLIT; s++) v += op[s * NB * DIM + idx];
    out[idx] = v;
}

// ------------------------------------------------------------------------------
extern "C" void kernel_launch(void* const* d_in, const int* in_sizes, int n_in,
                              void* d_out, int out_size)
{
    const float* x  = (const float*)d_in[0];
    const float* ck = (const float*)d_in[1];
    const float* cv = (const float*)d_in[2];
    const float* wq = (const float*)d_in[3];
    const float* wk = (const float*)d_in[4];
    const float* wv = (const float*)d_in[5];
    const float* wo = (const float*)d_in[6];
    const float* fc = (const float*)d_in[7];
    const float* fs = (const float*)d_in[8];
    float* out = (float*)d_out;

    float *qkvp, *qb, *kn, *vn, *pm, *pl, *pacc, *attn, *op;
    cudaGetSymbolAddress((void**)&qkvp, g_qkvp);
    cudaGetSymbolAddress((void**)&qb,   g_q);
    cudaGetSymbolAddress((void**)&kn,   g_kn);
    cudaGetSymbolAddress((void**)&vn,   g_vn);
    cudaGetSymbolAddress((void**)&pm,   g_pm);
    cudaGetSymbolAddress((void**)&pl,   g_pl);
    cudaGetSymbolAddress((void**)&pacc, g_pacc);
    cudaGetSymbolAddress((void**)&attn, g_attn);
    cudaGetSymbolAddress((void**)&op,   g_op);

    // 1) fused QKV projection (k-split partials, f32x2, pipelined)
    gemm_xwT<<<dim3(QKV_OUTS / 256, KSPLIT), 128>>>(x, wq, wk, wv, DIM, KVD, qkvp, QKV_OUTS);
    // 2) reduce partials + RoPE
    rope_reduce<<<384, 256>>>(qkvp, fc, fs, qb, kn, vn);
    // 3) split attention over cached tokens (pos 4095 masked)
    attn_split<<<dim3(NB * HKV, NSPLIT), 256>>>(qb, ck, cv, pm, pl, pacc);
    // 4) combine + new token
    attn_combine<<<dim3(NB * HKV, NREP), 128>>>(qb, kn, vn, pm, pl, pacc, attn);
    // 5) output projection (k-split partials, f32x2, pipelined)
    gemm_xwT<<<dim3(DIM / 256, KSPLIT), 128>>>(attn, wo, wo, wo, DIM, 0, op, DIM);
    // 6) reduce to d_out
    final_reduce<<<512, 256>>>(op, out);
}